// round 3
// baseline (speedup 1.0000x reference)
#include <cuda_runtime.h>
#include <cuda_bf16.h>

// MedianFilter: out = normalize( median7x7( clip(unnormalize(image), 0, 1) ) ), mask passthrough.
// image: [8,3,512,512] f32, mask: [8,1,512,512] f32, kernel_size: int (=7, hardcoded)
// Output buffer: [image-sized result][mask copy]

#define K      7
#define PAD    3
#define W      512
#define H      512
#define TSX    32
#define TSY    8
#define SMX    (TSX + K - 1)   // 38
#define SMY    (TSY + K - 1)   // 14
#define SMSTR  (SMX + 1)       // 39, pad stride

__device__ __forceinline__ void ce(float &x, float &y) {
    // compare-exchange: multiset-preserving (x=min, y=max)
    float lo = fminf(x, y);
    float hi = fmaxf(x, y);
    x = lo; y = hi;
}

__global__ __launch_bounds__(TSX * TSY)
void median7_kernel(const float* __restrict__ in, float* __restrict__ out, int planes) {
    __shared__ float tile[SMY][SMSTR];

    const int plane = blockIdx.z;
    const int c = plane % 3;
    const float mean = (c == 0) ? 0.485f : (c == 1) ? 0.456f : 0.406f;
    const float stdv = (c == 0) ? 0.229f : (c == 1) ? 0.224f : 0.225f;
    const float inv_std = 1.0f / stdv;

    const int x0 = blockIdx.x * TSX;
    const int y0 = blockIdx.y * TSY;
    const float* __restrict__ p = in + (size_t)plane * (W * H);

    // Cooperative halo-tile load with reflect padding + fused unnormalize+clamp
    const int tid = threadIdx.y * TSX + threadIdx.x;
    #pragma unroll
    for (int i = tid; i < SMY * SMX; i += TSX * TSY) {
        int ly = i / SMX, lx = i % SMX;
        int gy = y0 + ly - PAD;
        int gx = x0 + lx - PAD;
        gy = (gy < 0) ? -gy : ((gy >= H) ? (2 * H - 2 - gy) : gy);
        gx = (gx < 0) ? -gx : ((gx >= W) ? (2 * W - 2 - gx) : gx);
        float v = fmaf(p[gy * W + gx], stdv, mean);
        v = fminf(fmaxf(v, 0.0f), 1.0f);
        tile[ly][lx] = v;
    }
    __syncthreads();

    const int tx = threadIdx.x;
    const int ty = threadIdx.y;

    // Forgetful selection: buffer of 26, drop min&max + insert each round.
    float a[26];
    #pragma unroll
    for (int i = 0; i < 26; ++i)
        a[i] = tile[ty + i / 7][tx + i % 7];

    #pragma unroll
    for (int m = 26; m >= 4; --m) {
        // --- minmax network over a[0..m-1]: min -> a[0], max -> a[m-1] ---
        // pair phase
        #pragma unroll
        for (int i = 0; i + 1 < m; i += 2) ce(a[i], a[i + 1]);
        // min tree over even slots (covers lone a[m-1] when m odd)
        #pragma unroll
        for (int i = 2; i < m; i += 2) ce(a[0], a[i]);
        // max chain over odd slots
        #pragma unroll
        for (int i = 1; i + 2 < m; i += 2) ce(a[i], a[i + 2]);
        if (m & 1) ce(a[m - 2], a[m - 1]);  // finalize max at a[m-1] for odd m
        // drop max (slot m-1 dead), replace min with next window value
        const int nxt = 26 + (26 - m);      // 26..48, compile-time per unrolled iter
        a[0] = tile[ty + nxt / 7][tx + nxt % 7];
    }

    // median of remaining 3: a[0], a[1], a[2]
    ce(a[0], a[1]);
    const float med = fmaxf(a[0], fminf(a[1], a[2]));

    // renormalize: (med - mean) / std
    const float r = fmaf(med, inv_std, -mean * inv_std);
    out[(size_t)plane * (W * H) + (y0 + ty) * W + (x0 + tx)] = r;
}

__global__ void copy4_kernel(const float4* __restrict__ src, float4* __restrict__ dst, int n4) {
    int i = blockIdx.x * blockDim.x + threadIdx.x;
    if (i < n4) dst[i] = src[i];
}

extern "C" void kernel_launch(void* const* d_in, const int* in_sizes, int n_in,
                              void* d_out, int out_size) {
    const float* img  = (const float*)d_in[0];
    const float* mask = (const float*)d_in[1];
    float* out = (float*)d_out;

    const int img_n  = in_sizes[0];   // 8*3*512*512 = 6291456
    const int mask_n = in_sizes[1];   // 8*1*512*512 = 2097152
    const int planes = img_n / (W * H);  // 24

    dim3 block(TSX, TSY, 1);
    dim3 grid(W / TSX, H / TSY, planes);
    median7_kernel<<<grid, block>>>(img, out, planes);

    const int n4 = mask_n / 4;
    copy4_kernel<<<(n4 + 255) / 256, 256>>>((const float4*)mask, (float4*)(out + img_n), n4);
}